// round 2
// baseline (speedup 1.0000x reference)
#include <cuda_runtime.h>
#include <cuda_bf16.h>
#include <cstdio>

// ---------------------------------------------------------------------------
// GraphConv stack: 14 layers of  y = X@W0^T + b0 ;  n = X@W1^T + b1 ;
// y += scatter_add(n over undirected edges) ; relu (except final layer).
// N=100000 nodes, D=128, E=300000 edges, 12 hidden layers, final 128->3.
// ---------------------------------------------------------------------------

#define D 128
#define MAXN 100352   // >= N, multiple of 128

// Scratch (device globals: no allocation allowed)
__device__ float g_x  [(size_t)MAXN * D];   // current activations (relu'd)
__device__ float g_y  [(size_t)MAXN * D];   // self-transform + aggregation
__device__ float g_n  [(size_t)MAXN * D];   // neighbor transform
__device__ float g_res[(size_t)MAXN * D];   // residual (after first layer)
__device__ float g_n3 [(size_t)MAXN * 3];   // final-layer neighbor transform

// ---------------------------------------------------------------------------
// Dual GEMM:  Out[r, c] = sum_k X[r,k] * W[c,k] + b[c]
// blockIdx.y == 0 -> (W0,b0)->Y ; blockIdx.y == 1 -> (W1,b1)->Nb
// Classic 128x128 tile, BK=16, 8x8 per thread, 256 threads.
// ---------------------------------------------------------------------------
__global__ __launch_bounds__(256) void gemm_dual(
    const float* __restrict__ X,
    const float* __restrict__ W0, const float* __restrict__ b0,
    const float* __restrict__ W1, const float* __restrict__ b1,
    float* __restrict__ Y, float* __restrict__ Nb, int nrows)
{
    const float* W    = (blockIdx.y == 0) ? W0 : W1;
    const float* bias = (blockIdx.y == 0) ? b0 : b1;
    float*       Out  = (blockIdx.y == 0) ? Y  : Nb;

    __shared__ float As[16][D + 4];   // [k][m]
    __shared__ float Bs[16][D + 4];   // [k][n]

    const int tid  = threadIdx.x;        // 0..255
    const int row0 = blockIdx.x * 128;
    const int tx   = tid & 15;           // 0..15
    const int ty   = tid >> 4;           // 0..15

    float acc[8][8];
#pragma unroll
    for (int i = 0; i < 8; i++)
#pragma unroll
        for (int j = 0; j < 8; j++) acc[i][j] = 0.f;

    for (int k0 = 0; k0 < D; k0 += 16) {
        // Load A tile: 128 rows x 16 k = 512 float4 -> 2 per thread
#pragma unroll
        for (int it = 0; it < 2; it++) {
            int idx = tid + it * 256;          // 0..511
            int m   = idx >> 2;                // 0..127
            int kq  = idx & 3;                 // float4 within 16 k's
            int r   = row0 + m;
            float4 v = make_float4(0.f, 0.f, 0.f, 0.f);
            if (r < nrows)
                v = *(const float4*)(X + (size_t)r * D + k0 + kq * 4);
            As[kq * 4 + 0][m] = v.x;
            As[kq * 4 + 1][m] = v.y;
            As[kq * 4 + 2][m] = v.z;
            As[kq * 4 + 3][m] = v.w;
        }
        // Load B tile: W[c, k] ; 128 cols x 16 k
#pragma unroll
        for (int it = 0; it < 2; it++) {
            int idx = tid + it * 256;
            int c   = idx >> 2;
            int kq  = idx & 3;
            float4 v = *(const float4*)(W + (size_t)c * D + k0 + kq * 4);
            Bs[kq * 4 + 0][c] = v.x;
            Bs[kq * 4 + 1][c] = v.y;
            Bs[kq * 4 + 2][c] = v.z;
            Bs[kq * 4 + 3][c] = v.w;
        }
        __syncthreads();

#pragma unroll
        for (int kk = 0; kk < 16; kk++) {
            float a[8], b[8];
#pragma unroll
            for (int i = 0; i < 8; i++) a[i] = As[kk][ty * 8 + i];
#pragma unroll
            for (int j = 0; j < 8; j++) b[j] = Bs[kk][tx * 8 + j];
#pragma unroll
            for (int i = 0; i < 8; i++)
#pragma unroll
                for (int j = 0; j < 8; j++)
                    acc[i][j] = fmaf(a[i], b[j], acc[i][j]);
        }
        __syncthreads();
    }

#pragma unroll
    for (int i = 0; i < 8; i++) {
        int r = row0 + ty * 8 + i;
        if (r >= nrows) continue;
#pragma unroll
        for (int j = 0; j < 8; j++) {
            int c = tx * 8 + j;
            Out[(size_t)r * D + c] = acc[i][j] + bias[c];
        }
    }
}

// ---------------------------------------------------------------------------
// Undirected scatter: for each edge (i,j): Y[i,:] += Nb[j,:]; Y[j,:] += Nb[i,:]
// One warp per edge; each lane handles one float4 chunk (128/4 = 32 lanes).
// ---------------------------------------------------------------------------
__global__ __launch_bounds__(256) void scatter_add(
    const int* __restrict__ edges, const float* __restrict__ Nb,
    float* __restrict__ Y, int E)
{
    int g    = blockIdx.x * blockDim.x + threadIdx.x;
    int e    = g >> 5;
    int lane = g & 31;
    if (e >= E) return;
    int i = edges[2 * e];
    int j = edges[2 * e + 1];

    float4 vj = *(const float4*)(Nb + (size_t)j * D + lane * 4);
    float4 vi = *(const float4*)(Nb + (size_t)i * D + lane * 4);
    float* yi = Y + (size_t)i * D + lane * 4;
    float* yj = Y + (size_t)j * D + lane * 4;

    atomicAdd(yi + 0, vj.x); atomicAdd(yi + 1, vj.y);
    atomicAdd(yi + 2, vj.z); atomicAdd(yi + 3, vj.w);
    atomicAdd(yj + 0, vi.x); atomicAdd(yj + 1, vi.y);
    atomicAdd(yj + 2, vi.z); atomicAdd(yj + 3, vi.w);
}

// ---------------------------------------------------------------------------
// ReLU epilogue: X = relu(Y); optional residual / auxiliary copies.
// ---------------------------------------------------------------------------
__global__ __launch_bounds__(256) void relu_store(
    const float* __restrict__ Y, float* __restrict__ X,
    float* __restrict__ res, float* __restrict__ aux, int nquads)
{
    int idx = blockIdx.x * blockDim.x + threadIdx.x;
    if (idx >= nquads) return;
    float4 v = ((const float4*)Y)[idx];
    v.x = fmaxf(v.x, 0.f); v.y = fmaxf(v.y, 0.f);
    v.z = fmaxf(v.z, 0.f); v.w = fmaxf(v.w, 0.f);
    ((float4*)X)[idx] = v;
    if (res) ((float4*)res)[idx] = v;
    if (aux) ((float4*)aux)[idx] = v;
}

// ---------------------------------------------------------------------------
// Final layer (128 -> 3): z = res + x;  vert = z@W0^T + b0; n3 = z@W1^T + b1
// One thread per node.
// ---------------------------------------------------------------------------
__global__ __launch_bounds__(256) void final_gconv(
    const float* __restrict__ res, const float* __restrict__ x,
    const float* __restrict__ W0, const float* __restrict__ b0,
    const float* __restrict__ W1, const float* __restrict__ b1,
    float* __restrict__ vert, float* __restrict__ n3, int nrows)
{
    __shared__ float sW0[3 * D], sW1[3 * D], sb0[3], sb1[3];
    for (int t = threadIdx.x; t < 3 * D; t += blockDim.x) {
        sW0[t] = W0[t];
        sW1[t] = W1[t];
    }
    if (threadIdx.x < 3) {
        sb0[threadIdx.x] = b0[threadIdx.x];
        sb1[threadIdx.x] = b1[threadIdx.x];
    }
    __syncthreads();

    int node = blockIdx.x * blockDim.x + threadIdx.x;
    if (node >= nrows) return;

    const float4* r4 = (const float4*)(res + (size_t)node * D);
    const float4* x4 = (const float4*)(x   + (size_t)node * D);

    float accY[3] = {sb0[0], sb0[1], sb0[2]};
    float accN[3] = {sb1[0], sb1[1], sb1[2]};

#pragma unroll 8
    for (int q = 0; q < D / 4; q++) {
        float4 a = r4[q], b = x4[q];
        float z0 = a.x + b.x, z1 = a.y + b.y, z2 = a.z + b.z, z3 = a.w + b.w;
        int k = q * 4;
#pragma unroll
        for (int o = 0; o < 3; o++) {
            accY[o] = fmaf(z0, sW0[o * D + k + 0], accY[o]);
            accY[o] = fmaf(z1, sW0[o * D + k + 1], accY[o]);
            accY[o] = fmaf(z2, sW0[o * D + k + 2], accY[o]);
            accY[o] = fmaf(z3, sW0[o * D + k + 3], accY[o]);
            accN[o] = fmaf(z0, sW1[o * D + k + 0], accN[o]);
            accN[o] = fmaf(z1, sW1[o * D + k + 1], accN[o]);
            accN[o] = fmaf(z2, sW1[o * D + k + 2], accN[o]);
            accN[o] = fmaf(z3, sW1[o * D + k + 3], accN[o]);
        }
    }
#pragma unroll
    for (int o = 0; o < 3; o++) {
        vert[(size_t)node * 3 + o] = accY[o];
        n3  [(size_t)node * 3 + o] = accN[o];
    }
}

__global__ __launch_bounds__(256) void scatter3(
    const int* __restrict__ edges, const float* __restrict__ n3,
    float* __restrict__ vert, int E)
{
    int e = blockIdx.x * blockDim.x + threadIdx.x;
    if (e >= E) return;
    int i = edges[2 * e];
    int j = edges[2 * e + 1];
#pragma unroll
    for (int o = 0; o < 3; o++) {
        atomicAdd(&vert[(size_t)i * 3 + o], n3[(size_t)j * 3 + o]);
        atomicAdd(&vert[(size_t)j * 3 + o], n3[(size_t)i * 3 + o]);
    }
}

// ---------------------------------------------------------------------------
extern "C" void kernel_launch(void* const* d_in, const int* in_sizes, int n_in,
                              void* d_out, int out_size)
{
    const float* features = (const float*)d_in[0];
    const int*   edges    = (const int*)  d_in[1];
    const float* W0_1 = (const float*)d_in[2];
    const float* b0_1 = (const float*)d_in[3];
    const float* W1_1 = (const float*)d_in[4];
    const float* b1_1 = (const float*)d_in[5];
    const float* W0_h = (const float*)d_in[6];
    const float* b0_h = (const float*)d_in[7];
    const float* W1_h = (const float*)d_in[8];
    const float* b1_h = (const float*)d_in[9];
    const float* W0_l = (const float*)d_in[10];
    const float* b0_l = (const float*)d_in[11];
    const float* W1_l = (const float*)d_in[12];
    const float* b1_l = (const float*)d_in[13];

    const int Nn = in_sizes[0] / D;
    const int E  = in_sizes[1] / 2;
    const int Lh = in_sizes[6] / (D * D);

    float* out  = (float*)d_out;
    float* vert = out;                       // [N, 3]
    float* aux  = out + (size_t)Nn * 3;      // [N, 128]

    // Resolve scratch symbol addresses (host-side, not captured, no alloc).
    float *p_x, *p_y, *p_n, *p_res, *p_n3;
    cudaGetSymbolAddress((void**)&p_x,   g_x);
    cudaGetSymbolAddress((void**)&p_y,   g_y);
    cudaGetSymbolAddress((void**)&p_n,   g_n);
    cudaGetSymbolAddress((void**)&p_res, g_res);
    cudaGetSymbolAddress((void**)&p_n3,  g_n3);

    const dim3 gemm_grid((Nn + 127) / 128, 2);
    const int  scat_blocks  = (E * 32 + 255) / 256;
    const int  nquads       = Nn * D / 4;
    const int  relu_blocks  = (nquads + 255) / 256;
    const int  node_blocks  = (Nn + 255) / 256;
    const int  edge_blocks  = (E + 255) / 256;

    // ---- Layer 1: features -> x (relu), also residual -------------------
    gemm_dual<<<gemm_grid, 256>>>(features, W0_1, b0_1, W1_1, b1_1, p_y, p_n, Nn);
    scatter_add<<<scat_blocks, 256>>>(edges, p_n, p_y, E);
    relu_store<<<relu_blocks, 256>>>(p_y, p_x, p_res, nullptr, nquads);

    // ---- 12 hidden layers ------------------------------------------------
    for (int l = 0; l < Lh; l++) {
        const float* W0 = W0_h + (size_t)l * D * D;
        const float* b0 = b0_h + (size_t)l * D;
        const float* W1 = W1_h + (size_t)l * D * D;
        const float* b1 = b1_h + (size_t)l * D;
        gemm_dual<<<gemm_grid, 256>>>(p_x, W0, b0, W1, b1, p_y, p_n, Nn);
        scatter_add<<<scat_blocks, 256>>>(edges, p_n, p_y, E);
        float* aux_ptr = (l == Lh - 1) ? aux : nullptr;   // auxiliary output
        relu_store<<<relu_blocks, 256>>>(p_y, p_x, nullptr, aux_ptr, nquads);
    }

    // ---- Final layer: (res + x) -> vertices [N,3] ------------------------
    final_gconv<<<node_blocks, 256>>>(p_res, p_x, W0_l, b0_l, W1_l, b1_l,
                                      vert, p_n3, Nn);
    scatter3<<<edge_blocks, 256>>>(edges, p_n3, vert, E);
}

// round 3
// speedup vs baseline: 1.4985x; 1.4985x over previous
#include <cuda_runtime.h>
#include <cuda_bf16.h>
#include <cstdio>

// ---------------------------------------------------------------------------
// GraphConv stack: 14 layers of  y = X@W0^T + b0 ;  n = X@W1^T + b1 ;
// y += scatter_add(n over undirected edges) ; relu (except final layer).
// N=100000, D=128, E=300000, 12 hidden layers, final 128->3.
//
// R2: fused dual GEMM (shared A tile, relu-on-load, packed fma.rn.f32x2),
//     vectorized scatter (red.global.add.v4.f32), relu kernels eliminated.
// ---------------------------------------------------------------------------

#define D 128
#define MAXN 100352   // >= N, multiple of 128

typedef unsigned long long ull;

// Scratch (device globals: no allocation allowed)
__device__ __align__(128) float g_y1[(size_t)MAXN * D];  // layer-1 Y (pre-relu, post-scatter)
__device__ __align__(128) float g_ya[(size_t)MAXN * D];  // ping
__device__ __align__(128) float g_yb[(size_t)MAXN * D];  // pong
__device__ __align__(128) float g_n [(size_t)MAXN * D];  // neighbor transform
__device__ __align__(128) float g_n3[(size_t)MAXN * 3];  // final-layer neighbor transform

// ---- packed fp32x2 helpers (sm_103a) --------------------------------------
__device__ __forceinline__ ull pack2(float x, float y) {
    ull r;
    asm("mov.b64 %0, {%1, %2};" : "=l"(r) : "f"(x), "f"(y));
    return r;
}
__device__ __forceinline__ float2 unpack2(ull v) {
    float2 r;
    asm("mov.b64 {%0, %1}, %2;" : "=f"(r.x), "=f"(r.y) : "l"(v));
    return r;
}
#define FMA2(d, a, b) \
    asm volatile("fma.rn.f32x2 %0, %1, %2, %0;" : "+l"(d) : "l"(a), "l"(b))

// ---------------------------------------------------------------------------
// Fused dual GEMM: Y[r,c] = sum_k relu?(X[r,k]) * W0[c,k] + b0[c]
//                  Nb[r,c]= sum_k relu?(X[r,k]) * W1[c,k] + b1[c]
// One CTA: 128-row tile, both 128-col outputs. 256 threads, 8x(8+8) per thread
// via packed f32x2 accumulators (8 rows x 4 pairs x 2 outputs).
// ---------------------------------------------------------------------------
template <int RELU_A>
__global__ __launch_bounds__(256) void gemm_dual_fused(
    const float* __restrict__ X,
    const float* __restrict__ W0, const float* __restrict__ b0,
    const float* __restrict__ W1, const float* __restrict__ b1,
    float* __restrict__ Y, float* __restrict__ Nb, int nrows)
{
    __shared__ float As [16][D + 4];   // [k][m]
    __shared__ float B0s[16][D + 4];   // [k][c]
    __shared__ float B1s[16][D + 4];   // [k][c]

    const int tid  = threadIdx.x;        // 0..255
    const int row0 = blockIdx.x * 128;
    const int tx   = tid & 15;           // col group (8 cols)
    const int ty   = tid >> 4;           // row group (8 rows)

    ull acc0[8][4], acc1[8][4];
#pragma unroll
    for (int i = 0; i < 8; i++)
#pragma unroll
        for (int j = 0; j < 4; j++) { acc0[i][j] = 0ull; acc1[i][j] = 0ull; }

    for (int k0 = 0; k0 < D; k0 += 16) {
        // A tile: 128 rows x 16 k = 512 float4 -> 2 per thread
#pragma unroll
        for (int it = 0; it < 2; it++) {
            int idx = tid + it * 256;          // 0..511
            int m   = idx >> 2;                // 0..127
            int kq  = idx & 3;
            int r   = row0 + m;
            float4 v = make_float4(0.f, 0.f, 0.f, 0.f);
            if (r < nrows)
                v = *(const float4*)(X + (size_t)r * D + k0 + kq * 4);
            if (RELU_A) {
                v.x = fmaxf(v.x, 0.f); v.y = fmaxf(v.y, 0.f);
                v.z = fmaxf(v.z, 0.f); v.w = fmaxf(v.w, 0.f);
            }
            As[kq * 4 + 0][m] = v.x;
            As[kq * 4 + 1][m] = v.y;
            As[kq * 4 + 2][m] = v.z;
            As[kq * 4 + 3][m] = v.w;
        }
        // B tiles: W[c,k] ; 128 cols x 16 k each
#pragma unroll
        for (int it = 0; it < 2; it++) {
            int idx = tid + it * 256;
            int c   = idx >> 2;
            int kq  = idx & 3;
            float4 v0 = *(const float4*)(W0 + (size_t)c * D + k0 + kq * 4);
            float4 v1 = *(const float4*)(W1 + (size_t)c * D + k0 + kq * 4);
            B0s[kq * 4 + 0][c] = v0.x; B0s[kq * 4 + 1][c] = v0.y;
            B0s[kq * 4 + 2][c] = v0.z; B0s[kq * 4 + 3][c] = v0.w;
            B1s[kq * 4 + 0][c] = v1.x; B1s[kq * 4 + 1][c] = v1.y;
            B1s[kq * 4 + 2][c] = v1.z; B1s[kq * 4 + 3][c] = v1.w;
        }
        __syncthreads();

#pragma unroll
        for (int kk = 0; kk < 16; kk++) {
            // a: 8 rows, broadcast-packed into both halves
            float4 a0 = *(const float4*)&As[kk][ty * 8];
            float4 a1 = *(const float4*)&As[kk][ty * 8 + 4];
            ull a2[8];
            a2[0] = pack2(a0.x, a0.x); a2[1] = pack2(a0.y, a0.y);
            a2[2] = pack2(a0.z, a0.z); a2[3] = pack2(a0.w, a0.w);
            a2[4] = pack2(a1.x, a1.x); a2[5] = pack2(a1.y, a1.y);
            a2[6] = pack2(a1.z, a1.z); a2[7] = pack2(a1.w, a1.w);
            // b pairs: 4 per weight set
            float4 p0 = *(const float4*)&B0s[kk][tx * 8];
            float4 p1 = *(const float4*)&B0s[kk][tx * 8 + 4];
            float4 q0 = *(const float4*)&B1s[kk][tx * 8];
            float4 q1 = *(const float4*)&B1s[kk][tx * 8 + 4];
            ull b0p[4] = { pack2(p0.x, p0.y), pack2(p0.z, p0.w),
                           pack2(p1.x, p1.y), pack2(p1.z, p1.w) };
            ull b1p[4] = { pack2(q0.x, q0.y), pack2(q0.z, q0.w),
                           pack2(q1.x, q1.y), pack2(q1.z, q1.w) };
#pragma unroll
            for (int i = 0; i < 8; i++) {
#pragma unroll
                for (int j = 0; j < 4; j++) {
                    FMA2(acc0[i][j], a2[i], b0p[j]);
                    FMA2(acc1[i][j], a2[i], b1p[j]);
                }
            }
        }
        __syncthreads();
    }

    // epilogue: + bias, store as float4 pairs
    float4 bb0a = *(const float4*)&b0[tx * 8];
    float4 bb0b = *(const float4*)&b0[tx * 8 + 4];
    float4 bb1a = *(const float4*)&b1[tx * 8];
    float4 bb1b = *(const float4*)&b1[tx * 8 + 4];

#pragma unroll
    for (int i = 0; i < 8; i++) {
        int r = row0 + ty * 8 + i;
        if (r >= nrows) continue;
        float2 y0 = unpack2(acc0[i][0]), y1 = unpack2(acc0[i][1]);
        float2 y2 = unpack2(acc0[i][2]), y3 = unpack2(acc0[i][3]);
        float2 n0 = unpack2(acc1[i][0]), n1 = unpack2(acc1[i][1]);
        float2 n2 = unpack2(acc1[i][2]), n3 = unpack2(acc1[i][3]);
        float4 oy0 = make_float4(y0.x + bb0a.x, y0.y + bb0a.y, y1.x + bb0a.z, y1.y + bb0a.w);
        float4 oy1 = make_float4(y2.x + bb0b.x, y2.y + bb0b.y, y3.x + bb0b.z, y3.y + bb0b.w);
        float4 on0 = make_float4(n0.x + bb1a.x, n0.y + bb1a.y, n1.x + bb1a.z, n1.y + bb1a.w);
        float4 on1 = make_float4(n2.x + bb1b.x, n2.y + bb1b.y, n3.x + bb1b.z, n3.y + bb1b.w);
        *(float4*)(Y  + (size_t)r * D + tx * 8)     = oy0;
        *(float4*)(Y  + (size_t)r * D + tx * 8 + 4) = oy1;
        *(float4*)(Nb + (size_t)r * D + tx * 8)     = on0;
        *(float4*)(Nb + (size_t)r * D + tx * 8 + 4) = on1;
    }
}

// ---------------------------------------------------------------------------
// Undirected scatter with vector reductions: warp per edge, lane per float4.
// ---------------------------------------------------------------------------
__global__ __launch_bounds__(256) void scatter_add(
    const int2* __restrict__ edges, const float* __restrict__ Nb,
    float* __restrict__ Y, int E)
{
    int g    = blockIdx.x * blockDim.x + threadIdx.x;
    int e    = g >> 5;
    int lane = g & 31;
    if (e >= E) return;
    int2 ij = __ldg(&edges[e]);

    float4 vj = *(const float4*)(Nb + (size_t)ij.y * D + lane * 4);
    float4 vi = *(const float4*)(Nb + (size_t)ij.x * D + lane * 4);
    float* yi = Y + (size_t)ij.x * D + lane * 4;
    float* yj = Y + (size_t)ij.y * D + lane * 4;

    asm volatile("red.global.add.v4.f32 [%0], {%1,%2,%3,%4};"
                 :: "l"(yi), "f"(vj.x), "f"(vj.y), "f"(vj.z), "f"(vj.w) : "memory");
    asm volatile("red.global.add.v4.f32 [%0], {%1,%2,%3,%4};"
                 :: "l"(yj), "f"(vi.x), "f"(vi.y), "f"(vi.z), "f"(vi.w) : "memory");
}

// ---------------------------------------------------------------------------
// aux = relu(Y_last)  (single pass; fp32 output region)
// ---------------------------------------------------------------------------
__global__ __launch_bounds__(256) void relu_out(
    const float* __restrict__ Y, float* __restrict__ aux, int nquads)
{
    int idx = blockIdx.x * blockDim.x + threadIdx.x;
    if (idx >= nquads) return;
    float4 v = ((const float4*)Y)[idx];
    v.x = fmaxf(v.x, 0.f); v.y = fmaxf(v.y, 0.f);
    v.z = fmaxf(v.z, 0.f); v.w = fmaxf(v.w, 0.f);
    ((float4*)aux)[idx] = v;
}

// ---------------------------------------------------------------------------
// Final layer (128 -> 3): z = relu(y1) + relu(ylast)
//   vert = z@W0^T + b0 ; n3 = z@W1^T + b1. One thread per node.
// ---------------------------------------------------------------------------
__global__ __launch_bounds__(256) void final_gconv(
    const float* __restrict__ y1, const float* __restrict__ yl,
    const float* __restrict__ W0, const float* __restrict__ b0,
    const float* __restrict__ W1, const float* __restrict__ b1,
    float* __restrict__ vert, float* __restrict__ n3, int nrows)
{
    __shared__ float sW0[3 * D], sW1[3 * D], sb0[3], sb1[3];
    for (int t = threadIdx.x; t < 3 * D; t += blockDim.x) {
        sW0[t] = W0[t];
        sW1[t] = W1[t];
    }
    if (threadIdx.x < 3) {
        sb0[threadIdx.x] = b0[threadIdx.x];
        sb1[threadIdx.x] = b1[threadIdx.x];
    }
    __syncthreads();

    int node = blockIdx.x * blockDim.x + threadIdx.x;
    if (node >= nrows) return;

    const float4* r4 = (const float4*)(y1 + (size_t)node * D);
    const float4* x4 = (const float4*)(yl + (size_t)node * D);

    float accY[3] = {sb0[0], sb0[1], sb0[2]};
    float accN[3] = {sb1[0], sb1[1], sb1[2]};

#pragma unroll 8
    for (int q = 0; q < D / 4; q++) {
        float4 a = r4[q], b = x4[q];
        float z0 = fmaxf(a.x, 0.f) + fmaxf(b.x, 0.f);
        float z1 = fmaxf(a.y, 0.f) + fmaxf(b.y, 0.f);
        float z2 = fmaxf(a.z, 0.f) + fmaxf(b.z, 0.f);
        float z3 = fmaxf(a.w, 0.f) + fmaxf(b.w, 0.f);
        int k = q * 4;
#pragma unroll
        for (int o = 0; o < 3; o++) {
            accY[o] = fmaf(z0, sW0[o * D + k + 0], accY[o]);
            accY[o] = fmaf(z1, sW0[o * D + k + 1], accY[o]);
            accY[o] = fmaf(z2, sW0[o * D + k + 2], accY[o]);
            accY[o] = fmaf(z3, sW0[o * D + k + 3], accY[o]);
            accN[o] = fmaf(z0, sW1[o * D + k + 0], accN[o]);
            accN[o] = fmaf(z1, sW1[o * D + k + 1], accN[o]);
            accN[o] = fmaf(z2, sW1[o * D + k + 2], accN[o]);
            accN[o] = fmaf(z3, sW1[o * D + k + 3], accN[o]);
        }
    }
#pragma unroll
    for (int o = 0; o < 3; o++) {
        vert[(size_t)node * 3 + o] = accY[o];
        n3  [(size_t)node * 3 + o] = accN[o];
    }
}

__global__ __launch_bounds__(256) void scatter3(
    const int2* __restrict__ edges, const float* __restrict__ n3,
    float* __restrict__ vert, int E)
{
    int e = blockIdx.x * blockDim.x + threadIdx.x;
    if (e >= E) return;
    int2 ij = __ldg(&edges[e]);
#pragma unroll
    for (int o = 0; o < 3; o++) {
        atomicAdd(&vert[(size_t)ij.x * 3 + o], n3[(size_t)ij.y * 3 + o]);
        atomicAdd(&vert[(size_t)ij.y * 3 + o], n3[(size_t)ij.x * 3 + o]);
    }
}

// ---------------------------------------------------------------------------
extern "C" void kernel_launch(void* const* d_in, const int* in_sizes, int n_in,
                              void* d_out, int out_size)
{
    const float* features = (const float*)d_in[0];
    const int2*  edges    = (const int2*) d_in[1];
    const float* W0_1 = (const float*)d_in[2];
    const float* b0_1 = (const float*)d_in[3];
    const float* W1_1 = (const float*)d_in[4];
    const float* b1_1 = (const float*)d_in[5];
    const float* W0_h = (const float*)d_in[6];
    const float* b0_h = (const float*)d_in[7];
    const float* W1_h = (const float*)d_in[8];
    const float* b1_h = (const float*)d_in[9];
    const float* W0_l = (const float*)d_in[10];
    const float* b0_l = (const float*)d_in[11];
    const float* W1_l = (const float*)d_in[12];
    const float* b1_l = (const float*)d_in[13];

    const int Nn = in_sizes[0] / D;
    const int E  = in_sizes[1] / 2;
    const int Lh = in_sizes[6] / (D * D);

    float* out  = (float*)d_out;
    float* vert = out;                       // [N, 3]
    float* aux  = out + (size_t)Nn * 3;      // [N, 128]

    float *p_y1, *p_ya, *p_yb, *p_n, *p_n3;
    cudaGetSymbolAddress((void**)&p_y1, g_y1);
    cudaGetSymbolAddress((void**)&p_ya, g_ya);
    cudaGetSymbolAddress((void**)&p_yb, g_yb);
    cudaGetSymbolAddress((void**)&p_n,  g_n);
    cudaGetSymbolAddress((void**)&p_n3, g_n3);

    const int gemm_blocks  = (Nn + 127) / 128;
    const int scat_blocks  = (E * 32 + 255) / 256;
    const int nquads       = Nn * D / 4;
    const int relu_blocks  = (nquads + 255) / 256;
    const int node_blocks  = (Nn + 255) / 256;
    const int edge_blocks  = (E + 255) / 256;

    // ---- Layer 1: features -> g_y1 (pre-relu; relu applied by consumers) --
    gemm_dual_fused<0><<<gemm_blocks, 256>>>(features, W0_1, b0_1, W1_1, b1_1,
                                             p_y1, p_n, Nn);
    scatter_add<<<scat_blocks, 256>>>(edges, p_n, p_y1, E);

    // ---- 12 hidden layers: relu folded into A-load -----------------------
    const float* src = p_y1;
    float* dst = p_ya;
    for (int l = 0; l < Lh; l++) {
        const float* W0 = W0_h + (size_t)l * D * D;
        const float* b0 = b0_h + (size_t)l * D;
        const float* W1 = W1_h + (size_t)l * D * D;
        const float* b1 = b1_h + (size_t)l * D;
        gemm_dual_fused<1><<<gemm_blocks, 256>>>(src, W0, b0, W1, b1,
                                                 dst, p_n, Nn);
        scatter_add<<<scat_blocks, 256>>>(edges, p_n, dst, E);
        src = dst;
        dst = (dst == p_ya) ? p_yb : p_ya;
    }
    // src now points at last hidden layer's Y (pre-relu)
    const float* ylast = src;

    // ---- auxiliary output = relu(ylast) -----------------------------------
    relu_out<<<relu_blocks, 256>>>(ylast, aux, nquads);

    // ---- Final layer: (relu(y1) + relu(ylast)) -> vertices [N,3] ----------
    final_gconv<<<node_blocks, 256>>>(p_y1, ylast, W0_l, b0_l, W1_l, b1_l,
                                      vert, p_n3, Nn);
    scatter3<<<edge_blocks, 256>>>(edges, p_n3, vert, E);
}

// round 6
// speedup vs baseline: 2.7552x; 1.8386x over previous
#include <cuda_runtime.h>
#include <cuda_bf16.h>
#include <cstdint>

// ---------------------------------------------------------------------------
// GraphConv stack via mma.sync (HMMA bf16, 3-term split for fp32 precision).
// 14 layers: Y = X@W0^T+b0 ; Nb = X@W1^T+b1 ; Y += scatter(Nb, edges) ; relu.
// N=100000, D=128, E=300000. tcgen05 is unavailable (harness targets sm_103
// without the 'a' feature suffix), so tensor work goes through mma.sync.
// R6: fix A-tile conversion indexing (was written for 128 threads, kernel
// launches 256 -> OOB smem writes corrupted A_lo + weight tiles -> NaN).
// ---------------------------------------------------------------------------

#define D 128
#define MAXN 100352
#define MAXL 16

typedef unsigned int uint32;

// Scratch (device globals: no allocation allowed)
__device__ __align__(128) float g_y1[(size_t)MAXN * D];
__device__ __align__(128) float g_ya[(size_t)MAXN * D];
__device__ __align__(128) float g_yb[(size_t)MAXN * D];
__device__ __align__(128) float g_n [(size_t)MAXN * D];
__device__ __align__(128) float g_n3[(size_t)MAXN * 3];
// Pre-swizzled bf16 weight images: per layer {W0hi, W0lo, W1hi, W1lo}
__device__ __align__(128) __nv_bfloat16 g_wimg[(size_t)MAXL * 4 * D * D];

// ---------------- helpers ---------------------------------------------------
__device__ __forceinline__ uint32 smem_to_u32(const void* p) {
    uint32 a;
    asm("{ .reg .u64 t; cvta.to.shared.u64 t, %1; cvt.u32.u64 %0, t; }"
        : "=r"(a) : "l"(p));
    return a;
}
__device__ __forceinline__ void ldm_x4(uint32 a, uint32* r) {
    asm volatile("ldmatrix.sync.aligned.m8n8.x4.shared.b16 {%0,%1,%2,%3}, [%4];"
                 : "=r"(r[0]), "=r"(r[1]), "=r"(r[2]), "=r"(r[3]) : "r"(a));
}
__device__ __forceinline__ void mma_bf16(float* d, const uint32* a, const uint32* b) {
    asm volatile(
        "mma.sync.aligned.m16n8k16.row.col.f32.bf16.bf16.f32 "
        "{%0,%1,%2,%3}, {%4,%5,%6,%7}, {%8,%9}, {%0,%1,%2,%3};"
        : "+f"(d[0]), "+f"(d[1]), "+f"(d[2]), "+f"(d[3])
        : "r"(a[0]), "r"(a[1]), "r"(a[2]), "r"(a[3]), "r"(b[0]), "r"(b[1]));
}
#define CP_ASYNC16(dst, src) \
    asm volatile("cp.async.cg.shared.global [%0], [%1], 16;" \
                 :: "r"(dst), "l"(src) : "memory")
#define CP_COMMIT() asm volatile("cp.async.commit_group;" ::: "memory")
#define CP_WAIT0()  asm volatile("cp.async.wait_group 0;" ::: "memory")

// Swizzled tile layout for a 128x128 bf16 k-major matrix (32KB):
// row r (0..127), 16B chunk c (0..15):  off = r*256 + ((c ^ (r&7)) << 4)
__host__ __device__ __forceinline__ uint32 tile_off(int r, int c) {
    return (uint32)(r * 256 + (((c) ^ (r & 7)) << 4));
}

// SMEM layout (dynamic): A_hi 32KB | A_lo 32KB | B (4 x 32KB)
#define SM_AHI 0
#define SM_ALO 32768
#define SM_B   65536
#define SM_TOTAL (65536 + 131072)   // 192 KB

// ---------------------------------------------------------------------------
// Weight prep: split fp32 W (128x128, row=out-col, k contiguous) into bf16
// hi/lo, stored in the swizzled tile-image layout (linear cp.async at use).
// blockIdx.x enumerates 2*(Lh+1) matrices.
// ---------------------------------------------------------------------------
__global__ __launch_bounds__(256) void convert_weights(
    const float* __restrict__ W0_1, const float* __restrict__ W1_1,
    const float* __restrict__ W0_h, const float* __restrict__ W1_h,
    __nv_bfloat16* __restrict__ wimg)
{
    int m = blockIdx.x;
    int layer = m >> 1, sel = m & 1;
    const float* src;
    if (layer == 0) src = sel ? W1_1 : W0_1;
    else            src = (sel ? W1_h : W0_h) + (size_t)(layer - 1) * D * D;
    char* hi = (char*)(wimg + ((size_t)layer * 4 + sel * 2) * (D * D));
    char* lo = hi + D * D * 2;

    for (int e = threadIdx.x; e < 2048; e += blockDim.x) {   // 16B chunks
        int r = e >> 4, c = e & 15;
        const float* s = src + r * D + c * 8;
        uint32 h[4], l[4];
#pragma unroll
        for (int q = 0; q < 4; q++) {
            float x0 = s[q * 2], x1 = s[q * 2 + 1];
            __nv_bfloat16 h0 = __float2bfloat16(x0), h1 = __float2bfloat16(x1);
            __nv_bfloat16 l0 = __float2bfloat16(x0 - __bfloat162float(h0));
            __nv_bfloat16 l1 = __float2bfloat16(x1 - __bfloat162float(h1));
            __nv_bfloat162 hp = __halves2bfloat162(h0, h1);
            __nv_bfloat162 lp = __halves2bfloat162(l0, l1);
            h[q] = *(uint32*)&hp;
            l[q] = *(uint32*)&lp;
        }
        uint32 off = tile_off(r, c);
        *(uint4*)(hi + off) = make_uint4(h[0], h[1], h[2], h[3]);
        *(uint4*)(lo + off) = make_uint4(l[0], l[1], l[2], l[3]);
    }
}

// ---------------------------------------------------------------------------
// HMMA dual GEMM. CTA: 128 rows, 256 threads (8 warps, 2M x 4N warp grid,
// warp tile 64x32). Per output: 8 k-steps x (4m x 4n x 3 terms) mma.
// ---------------------------------------------------------------------------
template <int RELU>
__global__ __launch_bounds__(256) void gemm_tc(
    const float* __restrict__ X,
    const __nv_bfloat16* __restrict__ wimg,    // W0hi,W0lo,W1hi,W1lo images
    const float* __restrict__ b0, const float* __restrict__ b1,
    float* __restrict__ Y, float* __restrict__ Nb, int nrows)
{
    extern __shared__ char smem[];
    const uint32 sb = smem_to_u32(smem);
    const int tid  = threadIdx.x;
    const int wid  = tid >> 5;
    const int lane = tid & 31;
    const int row0 = blockIdx.x * 128;

    // ---- B: linear async copy of 128KB pre-swizzled weight image ----------
    {
        const char* src = (const char*)wimg;
#pragma unroll
        for (int i = 0; i < 32; i++) {
            uint32 off = (uint32)(tid + i * 256) * 16;
            CP_ASYNC16(sb + SM_B + off, src + off);
        }
        CP_COMMIT();
    }

    // ---- A: fp32 load (+relu), split to bf16 hi/lo, swizzled STS ----------
    // 128 rows x 32 float4/row = 4096 chunks, 256 threads -> 16 iterations.
#pragma unroll 4
    for (int it = 0; it < 16; it++) {
        int idx = tid + it * 256;            // float4 index, 0..4095
        int r   = idx >> 5;
        int cq  = idx & 31;                  // float4 within row
        int gr  = row0 + r;
        float4 v = make_float4(0.f, 0.f, 0.f, 0.f);
        if (gr < nrows) v = *(const float4*)(X + (size_t)gr * D + cq * 4);
        if (RELU) {
            v.x = fmaxf(v.x, 0.f); v.y = fmaxf(v.y, 0.f);
            v.z = fmaxf(v.z, 0.f); v.w = fmaxf(v.w, 0.f);
        }
        __nv_bfloat16 hx = __float2bfloat16(v.x), hy = __float2bfloat16(v.y);
        __nv_bfloat16 hz = __float2bfloat16(v.z), hw = __float2bfloat16(v.w);
        __nv_bfloat16 lx = __float2bfloat16(v.x - __bfloat162float(hx));
        __nv_bfloat16 ly = __float2bfloat16(v.y - __bfloat162float(hy));
        __nv_bfloat16 lz = __float2bfloat16(v.z - __bfloat162float(hz));
        __nv_bfloat16 lw = __float2bfloat16(v.w - __bfloat162float(hw));
        __nv_bfloat162 h0 = __halves2bfloat162(hx, hy), h1 = __halves2bfloat162(hz, hw);
        __nv_bfloat162 l0 = __halves2bfloat162(lx, ly), l1 = __halves2bfloat162(lz, lw);
        uint32 off = tile_off(r, cq >> 1) + (cq & 1) * 8;
        *(uint2*)(smem + SM_AHI + off) = make_uint2(*(uint32*)&h0, *(uint32*)&h1);
        *(uint2*)(smem + SM_ALO + off) = make_uint2(*(uint32*)&l0, *(uint32*)&l1);
    }
    CP_WAIT0();
    __syncthreads();

    // ---- compute -----------------------------------------------------------
    const int warpM = wid >> 2;          // 0..1  -> m0 = warpM*64
    const int warpN = wid & 3;           // 0..3  -> n0 = warpN*32
    const int g  = lane >> 3;            // ldmatrix group
    const int r8 = lane & 7;

    // A frag addresses: row = warpM*64 + i*16 + ((g&1)<<3) + r8, chunk = 2k+(g>>1)
    const int rowA = warpM * 64 + ((g & 1) << 3) + r8;
    const int swzA = rowA & 7;
    uint32 aBase[4];
#pragma unroll
    for (int i = 0; i < 4; i++) aBase[i] = sb + SM_AHI + (uint32)(rowA + i * 16) * 256;

    // B frag addresses: row = warpN*32 + jj*16 + ((g>>1)<<3) + r8, chunk = 2k+(g&1)
    const int rowB = warpN * 32 + ((g >> 1) << 3) + r8;
    const int swzB = rowB & 7;
    uint32 bBase[2];
#pragma unroll
    for (int jj = 0; jj < 2; jj++) bBase[jj] = sb + SM_B + (uint32)(rowB + jj * 16) * 256;

    for (int o = 0; o < 2; o++) {
        float acc[4][4][4];
#pragma unroll
        for (int i = 0; i < 4; i++)
#pragma unroll
            for (int j = 0; j < 4; j++)
#pragma unroll
                for (int q = 0; q < 4; q++) acc[i][j][q] = 0.f;

        const uint32 bOut = (uint32)o * 65536;

#pragma unroll
        for (int k = 0; k < 8; k++) {
            const uint32 offA = (uint32)(((2 * k + (g >> 1)) ^ swzA) << 4);
            const uint32 offB = (uint32)(((2 * k + (g & 1)) ^ swzB) << 4);

            uint32 ah[4][4], al[4][4];
#pragma unroll
            for (int i = 0; i < 4; i++) {
                ldm_x4(aBase[i] + offA, ah[i]);
                ldm_x4(aBase[i] + offA + 32768, al[i]);   // A_lo
            }
            uint32 bh[2][4], bl[2][4];
#pragma unroll
            for (int jj = 0; jj < 2; jj++) {
                ldm_x4(bBase[jj] + bOut + offB, bh[jj]);
                ldm_x4(bBase[jj] + bOut + offB + 32768, bl[jj]);  // W_lo
            }
#pragma unroll
            for (int i = 0; i < 4; i++) {
#pragma unroll
                for (int j = 0; j < 4; j++) {
                    const uint32* Bh = &bh[j >> 1][(j & 1) * 2];
                    const uint32* Bl = &bl[j >> 1][(j & 1) * 2];
                    mma_bf16(acc[i][j], ah[i], Bh);   // hi * Whi
                    mma_bf16(acc[i][j], ah[i], Bl);   // hi * Wlo
                    mma_bf16(acc[i][j], al[i], Bh);   // lo * Whi
                }
            }
        }

        // epilogue: + bias, direct float2 stores
        const float* bias = o ? b1 : b0;
        float*       O    = o ? Nb : Y;
#pragma unroll
        for (int j = 0; j < 4; j++) {
            int nc = warpN * 32 + j * 8 + (lane & 3) * 2;
            float bx = __ldg(bias + nc), by = __ldg(bias + nc + 1);
#pragma unroll
            for (int i = 0; i < 4; i++) {
                int r1 = row0 + warpM * 64 + i * 16 + (lane >> 2);
                int r2 = r1 + 8;
                if (r1 < nrows)
                    *(float2*)(O + (size_t)r1 * D + nc) =
                        make_float2(acc[i][j][0] + bx, acc[i][j][1] + by);
                if (r2 < nrows)
                    *(float2*)(O + (size_t)r2 * D + nc) =
                        make_float2(acc[i][j][2] + bx, acc[i][j][3] + by);
            }
        }
    }
}

// ---------------------------------------------------------------------------
// Undirected scatter: warp per edge, lane per float4, vector reductions.
// ---------------------------------------------------------------------------
__global__ __launch_bounds__(256) void scatter_add(
    const int2* __restrict__ edges, const float* __restrict__ Nb,
    float* __restrict__ Y, int E)
{
    int g    = blockIdx.x * blockDim.x + threadIdx.x;
    int e    = g >> 5;
    int lane = g & 31;
    if (e >= E) return;
    int2 ij = __ldg(&edges[e]);

    float4 vj = *(const float4*)(Nb + (size_t)ij.y * D + lane * 4);
    float4 vi = *(const float4*)(Nb + (size_t)ij.x * D + lane * 4);
    float* yi = Y + (size_t)ij.x * D + lane * 4;
    float* yj = Y + (size_t)ij.y * D + lane * 4;

    asm volatile("red.global.add.v4.f32 [%0], {%1,%2,%3,%4};"
                 :: "l"(yi), "f"(vj.x), "f"(vj.y), "f"(vj.z), "f"(vj.w) : "memory");
    asm volatile("red.global.add.v4.f32 [%0], {%1,%2,%3,%4};"
                 :: "l"(yj), "f"(vi.x), "f"(vi.y), "f"(vi.z), "f"(vi.w) : "memory");
}

// ---------------------------------------------------------------------------
__global__ __launch_bounds__(256) void relu_out(
    const float* __restrict__ Y, float* __restrict__ aux, int nquads)
{
    int idx = blockIdx.x * blockDim.x + threadIdx.x;
    if (idx >= nquads) return;
    float4 v = ((const float4*)Y)[idx];
    v.x = fmaxf(v.x, 0.f); v.y = fmaxf(v.y, 0.f);
    v.z = fmaxf(v.z, 0.f); v.w = fmaxf(v.w, 0.f);
    ((float4*)aux)[idx] = v;
}

// ---------------------------------------------------------------------------
// Final layer (128 -> 3): z = relu(y1) + relu(ylast);
//   vert = z@W0^T + b0 ; n3 = z@W1^T + b1. One thread per node.
// ---------------------------------------------------------------------------
__global__ __launch_bounds__(256) void final_gconv(
    const float* __restrict__ y1, const float* __restrict__ yl,
    const float* __restrict__ W0, const float* __restrict__ b0,
    const float* __restrict__ W1, const float* __restrict__ b1,
    float* __restrict__ vert, float* __restrict__ n3, int nrows)
{
    __shared__ float sW0[3 * D], sW1[3 * D], sb0[3], sb1[3];
    for (int t = threadIdx.x; t < 3 * D; t += blockDim.x) {
        sW0[t] = W0[t];
        sW1[t] = W1[t];
    }
    if (threadIdx.x < 3) {
        sb0[threadIdx.x] = b0[threadIdx.x];
        sb1[threadIdx.x] = b1[threadIdx.x];
    }
    __syncthreads();

    int node = blockIdx.x * blockDim.x + threadIdx.x;
    if (node >= nrows) return;

    const float4* r4 = (const float4*)(y1 + (size_t)node * D);
    const float4* x4 = (const float4*)(yl + (size_t)node * D);

    float accY[3] = {sb0[0], sb0[1], sb0[2]};
    float accN[3] = {sb1[0], sb1[1], sb1[2]};

#pragma unroll 8
    for (int q = 0; q < D / 4; q++) {
        float4 a = r4[q], b = x4[q];
        float z0 = fmaxf(a.x, 0.f) + fmaxf(b.x, 0.f);
        float z1 = fmaxf(a.y, 0.f) + fmaxf(b.y, 0.f);
        float z2 = fmaxf(a.z, 0.f) + fmaxf(b.z, 0.f);
        float z3 = fmaxf(a.w, 0.f) + fmaxf(b.w, 0.f);
        int k = q * 4;
#pragma unroll
        for (int o = 0; o < 3; o++) {
            accY[o] = fmaf(z0, sW0[o * D + k + 0], accY[o]);
            accY[o] = fmaf(z1, sW0[o * D + k + 1], accY[o]);
            accY[o] = fmaf(z2, sW0[o * D + k + 2], accY[o]);
            accY[o] = fmaf(z3, sW0[o * D + k + 3], accY[o]);
            accN[o] = fmaf(z0, sW1[o * D + k + 0], accN[o]);
            accN[o] = fmaf(z1, sW1[o * D + k + 1], accN[o]);
            accN[o] = fmaf(z2, sW1[o * D + k + 2], accN[o]);
            accN[o] = fmaf(z3, sW1[o * D + k + 3], accN[o]);
        }
    }
#pragma unroll
    for (int o = 0; o < 3; o++) {
        vert[(size_t)node * 3 + o] = accY[o];
        n3  [(size_t)node * 3 + o] = accN[o];
    }
}

__global__ __launch_bounds__(256) void scatter3(
    const int2* __restrict__ edges, const float* __restrict__ n3,
    float* __restrict__ vert, int E)
{
    int e = blockIdx.x * blockDim.x + threadIdx.x;
    if (e >= E) return;
    int2 ij = __ldg(&edges[e]);
#pragma unroll
    for (int o = 0; o < 3; o++) {
        atomicAdd(&vert[(size_t)ij.x * 3 + o], n3[(size_t)ij.y * 3 + o]);
        atomicAdd(&vert[(size_t)ij.y * 3 + o], n3[(size_t)ij.x * 3 + o]);
    }
}

// ---------------------------------------------------------------------------
extern "C" void kernel_launch(void* const* d_in, const int* in_sizes, int n_in,
                              void* d_out, int out_size)
{
    const float* features = (const float*)d_in[0];
    const int2*  edges    = (const int2*) d_in[1];
    const float* W0_1 = (const float*)d_in[2];
    const float* b0_1 = (const float*)d_in[3];
    const float* W1_1 = (const float*)d_in[4];
    const float* b1_1 = (const float*)d_in[5];
    const float* W0_h = (const float*)d_in[6];
    const float* b0_h = (const float*)d_in[7];
    const float* W1_h = (const float*)d_in[8];
    const float* b1_h = (const float*)d_in[9];
    const float* W0_l = (const float*)d_in[10];
    const float* b0_l = (const float*)d_in[11];
    const float* W1_l = (const float*)d_in[12];
    const float* b1_l = (const float*)d_in[13];

    const int Nn = in_sizes[0] / D;
    const int E  = in_sizes[1] / 2;
    const int Lh = in_sizes[6] / (D * D);

    float* out  = (float*)d_out;
    float* vert = out;                       // [N, 3]
    float* aux  = out + (size_t)Nn * 3;      // [N, 128]

    float *p_y1, *p_ya, *p_yb, *p_n, *p_n3;
    __nv_bfloat16* p_wimg;
    cudaGetSymbolAddress((void**)&p_y1,   g_y1);
    cudaGetSymbolAddress((void**)&p_ya,   g_ya);
    cudaGetSymbolAddress((void**)&p_yb,   g_yb);
    cudaGetSymbolAddress((void**)&p_n,    g_n);
    cudaGetSymbolAddress((void**)&p_n3,   g_n3);
    cudaGetSymbolAddress((void**)&p_wimg, g_wimg);

    cudaFuncSetAttribute(gemm_tc<0>, cudaFuncAttributeMaxDynamicSharedMemorySize, SM_TOTAL);
    cudaFuncSetAttribute(gemm_tc<1>, cudaFuncAttributeMaxDynamicSharedMemorySize, SM_TOTAL);

    const int gemm_blocks  = (Nn + 127) / 128;
    const int scat_blocks  = (E * 32 + 255) / 256;
    const int nquads       = Nn * D / 4;
    const int relu_blocks  = (nquads + 255) / 256;
    const int node_blocks  = (Nn + 255) / 256;
    const int edge_blocks  = (E + 255) / 256;

    // ---- Prepare split-bf16 swizzled weight images ------------------------
    convert_weights<<<2 * (Lh + 1), 256>>>(W0_1, W1_1, W0_h, W1_h, p_wimg);

    // ---- Layer 1: features -> g_y1 (pre-relu; consumers apply relu) -------
    gemm_tc<0><<<gemm_blocks, 256, SM_TOTAL>>>(
        features, p_wimg, b0_1, b1_1, p_y1, p_n, Nn);
    scatter_add<<<scat_blocks, 256>>>(edges, p_n, p_y1, E);

    // ---- 12 hidden layers: relu folded into A conversion ------------------
    const float* src = p_y1;
    float* dst = p_ya;
    for (int l = 0; l < Lh; l++) {
        const __nv_bfloat16* wl = p_wimg + (size_t)(l + 1) * 4 * D * D;
        const float* b0 = b0_h + (size_t)l * D;
        const float* b1 = b1_h + (size_t)l * D;
        gemm_tc<1><<<gemm_blocks, 256, SM_TOTAL>>>(src, wl, b0, b1, dst, p_n, Nn);
        scatter_add<<<scat_blocks, 256>>>(edges, p_n, dst, E);
        src = dst;
        dst = (dst == p_ya) ? p_yb : p_ya;
    }
    const float* ylast = src;

    // ---- auxiliary output = relu(ylast) ------------------------------------
    relu_out<<<relu_blocks, 256>>>(ylast, aux, nquads);

    // ---- Final layer: (relu(y1) + relu(ylast)) -> vertices [N,3] -----------
    final_gconv<<<node_blocks, 256>>>(p_y1, ylast, W0_l, b0_l, W1_l, b1_l,
                                      vert, p_n3, Nn);
    scatter3<<<edge_blocks, 256>>>(edges, p_n3, vert, E);
}

// round 7
// speedup vs baseline: 3.6758x; 1.3341x over previous
#include <cuda_runtime.h>
#include <cuda_bf16.h>
#include <cstdint>

// ---------------------------------------------------------------------------
// GraphConv stack via mma.sync (HMMA bf16, 3-term split => fp32 precision).
// R7: persistent double-buffered GEMM (weights loaded once per CTA, A tile
// pipeline) + CSR-based aggregation (no atomics in the hot path).
// ---------------------------------------------------------------------------

#define D 128
#define MAXN 100352
#define MAXE 310016
#define MAXL 16

typedef unsigned int uint32;

// Scratch (device globals: no allocation allowed)
__device__ __align__(128) float g_y1[(size_t)MAXN * D];
__device__ __align__(128) float g_ya[(size_t)MAXN * D];
__device__ __align__(128) float g_yb[(size_t)MAXN * D];
__device__ __align__(128) float g_n [(size_t)MAXN * D];
__device__ __align__(128) float g_n3[(size_t)MAXN * 3];
__device__ __align__(128) __nv_bfloat16 g_wimg[(size_t)MAXL * 4 * D * D];
// CSR scratch
__device__ int g_deg[MAXN];
__device__ int g_rowstart[MAXN];
__device__ int g_wr[MAXN];
__device__ int g_adj[2 * MAXE];
__device__ int g_cursor;

// ---------------- helpers ---------------------------------------------------
__device__ __forceinline__ uint32 smem_to_u32(const void* p) {
    uint32 a;
    asm("{ .reg .u64 t; cvta.to.shared.u64 t, %1; cvt.u32.u64 %0, t; }"
        : "=r"(a) : "l"(p));
    return a;
}
__device__ __forceinline__ void ldm_x4(uint32 a, uint32* r) {
    asm volatile("ldmatrix.sync.aligned.m8n8.x4.shared.b16 {%0,%1,%2,%3}, [%4];"
                 : "=r"(r[0]), "=r"(r[1]), "=r"(r[2]), "=r"(r[3]) : "r"(a));
}
__device__ __forceinline__ void mma_bf16(float* d, const uint32* a, const uint32* b) {
    asm volatile(
        "mma.sync.aligned.m16n8k16.row.col.f32.bf16.bf16.f32 "
        "{%0,%1,%2,%3}, {%4,%5,%6,%7}, {%8,%9}, {%0,%1,%2,%3};"
        : "+f"(d[0]), "+f"(d[1]), "+f"(d[2]), "+f"(d[3])
        : "r"(a[0]), "r"(a[1]), "r"(a[2]), "r"(a[3]), "r"(b[0]), "r"(b[1]));
}
#define CP_ASYNC16(dst, src) \
    asm volatile("cp.async.cg.shared.global [%0], [%1], 16;" \
                 :: "r"(dst), "l"(src) : "memory")
#define CP_COMMIT() asm volatile("cp.async.commit_group;" ::: "memory")
#define CP_WAIT0()  asm volatile("cp.async.wait_group 0;" ::: "memory")

// Swizzled tile layout for a [rows x 128] bf16 k-major matrix:
// row r, 16B chunk c (0..15):  off = r*256 + ((c ^ (r&7)) << 4)
__host__ __device__ __forceinline__ uint32 tile_off(int r, int c) {
    return (uint32)(r * 256 + (((c) ^ (r & 7)) << 4));
}

// SMEM: A double buffer 2 x (hi 16KB + lo 16KB) | B 4 x 32KB {W0h,W0l,W1h,W1l}
#define SM_ABUF  32768          // stride between A buffers
#define SM_ALO   16384          // lo offset within an A buffer
#define SM_B     65536
#define SM_TOTAL (65536 + 131072)   // 192 KB

// ---------------------------------------------------------------------------
// Weight prep: split fp32 W into bf16 hi/lo in the swizzled image layout.
// ---------------------------------------------------------------------------
__global__ __launch_bounds__(256) void convert_weights(
    const float* __restrict__ W0_1, const float* __restrict__ W1_1,
    const float* __restrict__ W0_h, const float* __restrict__ W1_h,
    __nv_bfloat16* __restrict__ wimg)
{
    int m = blockIdx.x;
    int layer = m >> 1, sel = m & 1;
    const float* src;
    if (layer == 0) src = sel ? W1_1 : W0_1;
    else            src = (sel ? W1_h : W0_h) + (size_t)(layer - 1) * D * D;
    char* hi = (char*)(wimg + ((size_t)layer * 4 + sel * 2) * (D * D));
    char* lo = hi + D * D * 2;

    for (int e = threadIdx.x; e < 2048; e += blockDim.x) {   // 16B chunks
        int r = e >> 4, c = e & 15;
        const float* s = src + r * D + c * 8;
        uint32 h[4], l[4];
#pragma unroll
        for (int q = 0; q < 4; q++) {
            float x0 = s[q * 2], x1 = s[q * 2 + 1];
            __nv_bfloat16 h0 = __float2bfloat16(x0), h1 = __float2bfloat16(x1);
            __nv_bfloat16 l0 = __float2bfloat16(x0 - __bfloat162float(h0));
            __nv_bfloat16 l1 = __float2bfloat16(x1 - __bfloat162float(h1));
            __nv_bfloat162 hp = __halves2bfloat162(h0, h1);
            __nv_bfloat162 lp = __halves2bfloat162(l0, l1);
            h[q] = *(uint32*)&hp;
            l[q] = *(uint32*)&lp;
        }
        uint32 off = tile_off(r, c);
        *(uint4*)(hi + off) = make_uint4(h[0], h[1], h[2], h[3]);
        *(uint4*)(lo + off) = make_uint4(l[0], l[1], l[2], l[3]);
    }
}

// ---- A tile helpers: 64 rows x 32 float4 = 2048 chunks / 256 thr = 8 each --
__device__ __forceinline__ void ldA(const float* __restrict__ X, int row0,
                                    int nrows, int tid, float4* pf) {
#pragma unroll
    for (int q = 0; q < 8; q++) {
        int idx = tid + q * 256;
        int r = idx >> 5, cq = idx & 31;
        int gr = row0 + r;
        float4 v = make_float4(0.f, 0.f, 0.f, 0.f);
        if (gr < nrows) v = __ldg((const float4*)(X + (size_t)gr * D + cq * 4));
        pf[q] = v;
    }
}
template <int RELU>
__device__ __forceinline__ void cvtA(char* smem, uint32 bufoff, int tid,
                                     const float4* pf) {
#pragma unroll
    for (int q = 0; q < 8; q++) {
        int idx = tid + q * 256;
        int r = idx >> 5, cq = idx & 31;
        float4 v = pf[q];
        if (RELU) {
            v.x = fmaxf(v.x, 0.f); v.y = fmaxf(v.y, 0.f);
            v.z = fmaxf(v.z, 0.f); v.w = fmaxf(v.w, 0.f);
        }
        __nv_bfloat16 hx = __float2bfloat16(v.x), hy = __float2bfloat16(v.y);
        __nv_bfloat16 hz = __float2bfloat16(v.z), hw = __float2bfloat16(v.w);
        __nv_bfloat16 lx = __float2bfloat16(v.x - __bfloat162float(hx));
        __nv_bfloat16 ly = __float2bfloat16(v.y - __bfloat162float(hy));
        __nv_bfloat16 lz = __float2bfloat16(v.z - __bfloat162float(hz));
        __nv_bfloat16 lw = __float2bfloat16(v.w - __bfloat162float(hw));
        __nv_bfloat162 h0 = __halves2bfloat162(hx, hy), h1 = __halves2bfloat162(hz, hw);
        __nv_bfloat162 l0 = __halves2bfloat162(lx, ly), l1 = __halves2bfloat162(lz, lw);
        uint32 off = tile_off(r, cq >> 1) + (cq & 1) * 8;
        *(uint2*)(smem + bufoff + off)          = make_uint2(*(uint32*)&h0, *(uint32*)&h1);
        *(uint2*)(smem + bufoff + SM_ALO + off) = make_uint2(*(uint32*)&l0, *(uint32*)&l1);
    }
}

// ---------------------------------------------------------------------------
// Persistent HMMA dual GEMM. grid = #SMs. Each CTA: load weights once, loop
// over 64-row tiles with a double-buffered A pipeline. 256 threads = 8 warps,
// warp grid 2M x 4N, warp tile 32x32.
// ---------------------------------------------------------------------------
template <int RELU>
__global__ __launch_bounds__(256) void gemm_tc(
    const float* __restrict__ X,
    const __nv_bfloat16* __restrict__ wimg,
    const float* __restrict__ b0, const float* __restrict__ b1,
    float* __restrict__ Y, float* __restrict__ Nb, int nrows)
{
    extern __shared__ char smem[];
    const uint32 sb = smem_to_u32(smem);
    const int tid  = threadIdx.x;
    const int wid  = tid >> 5;
    const int lane = tid & 31;
    const int ntiles = (nrows + 63) >> 6;

    // ---- B: one 128KB cp.async of the pre-swizzled weight image -----------
    {
        const char* src = (const char*)wimg;
#pragma unroll
        for (int i = 0; i < 32; i++) {
            uint32 off = (uint32)(tid + i * 256) * 16;
            CP_ASYNC16(sb + SM_B + off, src + off);
        }
        CP_COMMIT();
    }

    // ---- prologue: convert first tile into buffer 0 ------------------------
    {
        int t0 = blockIdx.x;
        if (t0 < ntiles) {
            float4 pf[8];
            ldA(X, t0 * 64, nrows, tid, pf);
            cvtA<RELU>(smem, 0, tid, pf);
        }
    }
    CP_WAIT0();
    __syncthreads();

    // ---- fragment addressing ------------------------------------------------
    const int warpM = wid >> 2;          // 0..1 -> 32 rows each
    const int warpN = wid & 3;           // 0..3 -> 32 cols each
    const int g  = lane >> 3;
    const int r8 = lane & 7;

    const int rowA = warpM * 32 + ((g & 1) << 3) + r8;
    const int swzA = rowA & 7;
    uint32 aRel[2];
#pragma unroll
    for (int i = 0; i < 2; i++) aRel[i] = (uint32)(rowA + i * 16) * 256;

    const int rowB = warpN * 32 + ((g >> 1) << 3) + r8;
    const int swzB = rowB & 7;
    uint32 bBase[2];
#pragma unroll
    for (int jj = 0; jj < 2; jj++)
        bBase[jj] = sb + SM_B + (uint32)(rowB + (jj << 4) - ((g >> 1) << 3) * 0) * 256;
    // (rowB already includes the (g>>1) lane-group shift; jj adds 16 rows)
#pragma unroll
    for (int jj = 0; jj < 2; jj++)
        bBase[jj] = sb + SM_B + (uint32)(rowB + jj * 16) * 256;

    // bias registers (layer-invariant across tiles)
    float bx[2][4], by[2][4];
#pragma unroll
    for (int o = 0; o < 2; o++) {
        const float* bias = o ? b1 : b0;
#pragma unroll
        for (int j = 0; j < 4; j++) {
            int nc = warpN * 32 + j * 8 + (lane & 3) * 2;
            bx[o][j] = __ldg(bias + nc);
            by[o][j] = __ldg(bias + nc + 1);
        }
    }

    // ---- main pipelined loop -------------------------------------------------
    int buf = 0;
    for (int t = blockIdx.x; t < ntiles; t += gridDim.x) {
        const int tn = t + gridDim.x;
        const bool have = tn < ntiles;
        float4 pf[8];
        if (have) ldA(X, tn * 64, nrows, tid, pf);   // LDG overlaps MMA below

        const uint32 abase = sb + (uint32)buf * SM_ABUF;
        const int row0 = t * 64;

#pragma unroll
        for (int o = 0; o < 2; o++) {
            float acc[2][4][4];
#pragma unroll
            for (int i = 0; i < 2; i++)
#pragma unroll
                for (int j = 0; j < 4; j++)
#pragma unroll
                    for (int q = 0; q < 4; q++) acc[i][j][q] = 0.f;

            const uint32 bOut = (uint32)o * 65536;

#pragma unroll
            for (int k = 0; k < 8; k++) {
                const uint32 offA = (uint32)(((2 * k + (g >> 1)) ^ swzA) << 4);
                const uint32 offB = (uint32)(((2 * k + (g & 1)) ^ swzB) << 4);

                uint32 ah[2][4], al[2][4];
#pragma unroll
                for (int i = 0; i < 2; i++) {
                    ldm_x4(abase + aRel[i] + offA, ah[i]);
                    ldm_x4(abase + aRel[i] + offA + SM_ALO, al[i]);
                }
                uint32 bh[2][4], bl[2][4];
#pragma unroll
                for (int jj = 0; jj < 2; jj++) {
                    ldm_x4(bBase[jj] + bOut + offB, bh[jj]);
                    ldm_x4(bBase[jj] + bOut + offB + 32768, bl[jj]);
                }
#pragma unroll
                for (int i = 0; i < 2; i++) {
#pragma unroll
                    for (int j = 0; j < 4; j++) {
                        const uint32* Bh = &bh[j >> 1][(j & 1) * 2];
                        const uint32* Bl = &bl[j >> 1][(j & 1) * 2];
                        mma_bf16(acc[i][j], ah[i], Bh);
                        mma_bf16(acc[i][j], ah[i], Bl);
                        mma_bf16(acc[i][j], al[i], Bh);
                    }
                }
            }

            float* O = o ? Nb : Y;
#pragma unroll
            for (int j = 0; j < 4; j++) {
                int nc = warpN * 32 + j * 8 + (lane & 3) * 2;
#pragma unroll
                for (int i = 0; i < 2; i++) {
                    int r1 = row0 + warpM * 32 + i * 16 + (lane >> 2);
                    int r2 = r1 + 8;
                    if (r1 < nrows)
                        *(float2*)(O + (size_t)r1 * D + nc) =
                            make_float2(acc[i][j][0] + bx[o][j], acc[i][j][1] + by[o][j]);
                    if (r2 < nrows)
                        *(float2*)(O + (size_t)r2 * D + nc) =
                            make_float2(acc[i][j][2] + bx[o][j], acc[i][j][3] + by[o][j]);
                }
            }
        }

        if (have) cvtA<RELU>(smem, (uint32)(buf ^ 1) * SM_ABUF, tid, pf);
        __syncthreads();
        buf ^= 1;
    }
}

// ---------------------------------------------------------------------------
// CSR build (once per call). Segment order is atomic-nondeterministic, which
// only permutes addition order inside a node's neighbor sum.
// ---------------------------------------------------------------------------
__global__ __launch_bounds__(256) void csr_zero(int* deg, int* cursor, int Nn) {
    int i = blockIdx.x * blockDim.x + threadIdx.x;
    if (i < Nn) deg[i] = 0;
    if (i == 0) *cursor = 0;
}
__global__ __launch_bounds__(256) void csr_count(const int2* __restrict__ edges,
                                                 int* deg, int E) {
    int e = blockIdx.x * blockDim.x + threadIdx.x;
    if (e >= E) return;
    int2 ij = __ldg(&edges[e]);
    atomicAdd(&deg[ij.x], 1);
    atomicAdd(&deg[ij.y], 1);
}
__global__ __launch_bounds__(256) void csr_offsets(const int* __restrict__ deg,
                                                   int* rowstart, int* wr,
                                                   int* cursor, int Nn) {
    int i = blockIdx.x * blockDim.x + threadIdx.x;
    if (i >= Nn) return;
    int s = atomicAdd(cursor, deg[i]);
    rowstart[i] = s;
    wr[i] = s;
}
__global__ __launch_bounds__(256) void csr_fill(const int2* __restrict__ edges,
                                                int* wr, int* adj, int E) {
    int e = blockIdx.x * blockDim.x + threadIdx.x;
    if (e >= E) return;
    int2 ij = __ldg(&edges[e]);
    adj[atomicAdd(&wr[ij.x], 1)] = ij.y;
    adj[atomicAdd(&wr[ij.y], 1)] = ij.x;
}

// ---------------------------------------------------------------------------
// Aggregation: one warp per node. Y[node] += sum_{nbr} Nb[nbr]. No atomics.
// ---------------------------------------------------------------------------
__global__ __launch_bounds__(256) void agg(
    const int* __restrict__ rowstart, const int* __restrict__ deg,
    const int* __restrict__ adj, const float* __restrict__ Nb,
    float* __restrict__ Y, int Nn)
{
    int gidx = blockIdx.x * blockDim.x + threadIdx.x;
    int node = gidx >> 5;
    int lane = gidx & 31;
    if (node >= Nn) return;
    int d = __ldg(&deg[node]);
    int base = __ldg(&rowstart[node]);

    float4 acc = make_float4(0.f, 0.f, 0.f, 0.f);
    int t = 0;
    for (; t + 2 <= d; t += 2) {
        int n0 = __ldg(&adj[base + t]);
        int n1 = __ldg(&adj[base + t + 1]);
        float4 v0 = __ldg((const float4*)(Nb + (size_t)n0 * D + lane * 4));
        float4 v1 = __ldg((const float4*)(Nb + (size_t)n1 * D + lane * 4));
        acc.x += v0.x + v1.x; acc.y += v0.y + v1.y;
        acc.z += v0.z + v1.z; acc.w += v0.w + v1.w;
    }
    if (t < d) {
        int n0 = __ldg(&adj[base + t]);
        float4 v0 = __ldg((const float4*)(Nb + (size_t)n0 * D + lane * 4));
        acc.x += v0.x; acc.y += v0.y; acc.z += v0.z; acc.w += v0.w;
    }
    float4* yp = (float4*)(Y + (size_t)node * D + lane * 4);
    float4 y = *yp;
    y.x += acc.x; y.y += acc.y; y.z += acc.z; y.w += acc.w;
    *yp = y;
}

// Final-layer aggregation over 3-wide rows: one thread per node, no atomics.
__global__ __launch_bounds__(256) void agg3(
    const int* __restrict__ rowstart, const int* __restrict__ deg,
    const int* __restrict__ adj, const float* __restrict__ n3,
    float* __restrict__ vert, int Nn)
{
    int node = blockIdx.x * blockDim.x + threadIdx.x;
    if (node >= Nn) return;
    int d = __ldg(&deg[node]);
    int base = __ldg(&rowstart[node]);
    float a0 = 0.f, a1 = 0.f, a2 = 0.f;
    for (int t = 0; t < d; t++) {
        int nbr = __ldg(&adj[base + t]);
        a0 += __ldg(&n3[(size_t)nbr * 3 + 0]);
        a1 += __ldg(&n3[(size_t)nbr * 3 + 1]);
        a2 += __ldg(&n3[(size_t)nbr * 3 + 2]);
    }
    vert[(size_t)node * 3 + 0] += a0;
    vert[(size_t)node * 3 + 1] += a1;
    vert[(size_t)node * 3 + 2] += a2;
}

// ---------------------------------------------------------------------------
__global__ __launch_bounds__(256) void relu_out(
    const float* __restrict__ Y, float* __restrict__ aux, int nquads)
{
    int idx = blockIdx.x * blockDim.x + threadIdx.x;
    if (idx >= nquads) return;
    float4 v = ((const float4*)Y)[idx];
    v.x = fmaxf(v.x, 0.f); v.y = fmaxf(v.y, 0.f);
    v.z = fmaxf(v.z, 0.f); v.w = fmaxf(v.w, 0.f);
    ((float4*)aux)[idx] = v;
}

// ---------------------------------------------------------------------------
// Final layer (128 -> 3): z = relu(y1) + relu(ylast);
//   vert = z@W0^T + b0 ; n3 = z@W1^T + b1. One thread per node.
// ---------------------------------------------------------------------------
__global__ __launch_bounds__(256) void final_gconv(
    const float* __restrict__ y1, const float* __restrict__ yl,
    const float* __restrict__ W0, const float* __restrict__ b0,
    const float* __restrict__ W1, const float* __restrict__ b1,
    float* __restrict__ vert, float* __restrict__ n3, int nrows)
{
    __shared__ float sW0[3 * D], sW1[3 * D], sb0[3], sb1[3];
    for (int t = threadIdx.x; t < 3 * D; t += blockDim.x) {
        sW0[t] = W0[t];
        sW1[t] = W1[t];
    }
    if (threadIdx.x < 3) {
        sb0[threadIdx.x] = b0[threadIdx.x];
        sb1[threadIdx.x] = b1[threadIdx.x];
    }
    __syncthreads();

    int node = blockIdx.x * blockDim.x + threadIdx.x;
    if (node >= nrows) return;

    const float4* r4 = (const float4*)(y1 + (size_t)node * D);
    const float4* x4 = (const float4*)(yl + (size_t)node * D);

    float accY[3] = {sb0[0], sb0[1], sb0[2]};
    float accN[3] = {sb1[0], sb1[1], sb1[2]};

#pragma unroll 8
    for (int q = 0; q < D / 4; q++) {
        float4 a = r4[q], b = x4[q];
        float z0 = fmaxf(a.x, 0.f) + fmaxf(b.x, 0.f);
        float z1 = fmaxf(a.y, 0.f) + fmaxf(b.y, 0.f);
        float z2 = fmaxf(a.z, 0.f) + fmaxf(b.z, 0.f);
        float z3 = fmaxf(a.w, 0.f) + fmaxf(b.w, 0.f);
        int k = q * 4;
#pragma unroll
        for (int o = 0; o < 3; o++) {
            accY[o] = fmaf(z0, sW0[o * D + k + 0], accY[o]);
            accY[o] = fmaf(z1, sW0[o * D + k + 1], accY[o]);
            accY[o] = fmaf(z2, sW0[o * D + k + 2], accY[o]);
            accY[o] = fmaf(z3, sW0[o * D + k + 3], accY[o]);
            accN[o] = fmaf(z0, sW1[o * D + k + 0], accN[o]);
            accN[o] = fmaf(z1, sW1[o * D + k + 1], accN[o]);
            accN[o] = fmaf(z2, sW1[o * D + k + 2], accN[o]);
            accN[o] = fmaf(z3, sW1[o * D + k + 3], accN[o]);
        }
    }
#pragma unroll
    for (int o = 0; o < 3; o++) {
        vert[(size_t)node * 3 + o] = accY[o];
        n3  [(size_t)node * 3 + o] = accN[o];
    }
}

// ---------------------------------------------------------------------------
extern "C" void kernel_launch(void* const* d_in, const int* in_sizes, int n_in,
                              void* d_out, int out_size)
{
    const float* features = (const float*)d_in[0];
    const int2*  edges    = (const int2*) d_in[1];
    const float* W0_1 = (const float*)d_in[2];
    const float* b0_1 = (const float*)d_in[3];
    const float* W1_1 = (const float*)d_in[4];
    const float* b1_1 = (const float*)d_in[5];
    const float* W0_h = (const float*)d_in[6];
    const float* b0_h = (const float*)d_in[7];
    const float* W1_h = (const float*)d_in[8];
    const float* b1_h = (const float*)d_in[9];
    const float* W0_l = (const float*)d_in[10];
    const float* b0_l = (const float*)d_in[11];
    const float* W1_l = (const float*)d_in[12];
    const float* b1_l = (const float*)d_in[13];

    const int Nn = in_sizes[0] / D;
    const int E  = in_sizes[1] / 2;
    const int Lh = in_sizes[6] / (D * D);

    float* out  = (float*)d_out;
    float* vert = out;                       // [N, 3]
    float* aux  = out + (size_t)Nn * 3;      // [N, 128]

    float *p_y1, *p_ya, *p_yb, *p_n, *p_n3;
    __nv_bfloat16* p_wimg;
    int *p_deg, *p_rs, *p_wr, *p_adj, *p_cur;
    cudaGetSymbolAddress((void**)&p_y1,   g_y1);
    cudaGetSymbolAddress((void**)&p_ya,   g_ya);
    cudaGetSymbolAddress((void**)&p_yb,   g_yb);
    cudaGetSymbolAddress((void**)&p_n,    g_n);
    cudaGetSymbolAddress((void**)&p_n3,   g_n3);
    cudaGetSymbolAddress((void**)&p_wimg, g_wimg);
    cudaGetSymbolAddress((void**)&p_deg,  g_deg);
    cudaGetSymbolAddress((void**)&p_rs,   g_rowstart);
    cudaGetSymbolAddress((void**)&p_wr,   g_wr);
    cudaGetSymbolAddress((void**)&p_adj,  g_adj);
    cudaGetSymbolAddress((void**)&p_cur,  g_cursor);

    cudaFuncSetAttribute(gemm_tc<0>, cudaFuncAttributeMaxDynamicSharedMemorySize, SM_TOTAL);
    cudaFuncSetAttribute(gemm_tc<1>, cudaFuncAttributeMaxDynamicSharedMemorySize, SM_TOTAL);

    int smc = 0;
    if (cudaDeviceGetAttribute(&smc, cudaDevAttrMultiProcessorCount, 0) != cudaSuccess
        || smc <= 0)
        smc = 148;

    const int ntiles      = (Nn + 63) / 64;
    const int gemm_grid   = smc < ntiles ? smc : ntiles;
    const int nquads      = Nn * D / 4;
    const int relu_blocks = (nquads + 255) / 256;
    const int node_blocks = (Nn + 255) / 256;
    const int edge_blocks = (E + 255) / 256;
    const int agg_blocks  = (Nn * 32 + 255) / 256;

    // ---- weight images + CSR build (independent precomputation) -----------
    convert_weights<<<2 * (Lh + 1), 256>>>(W0_1, W1_1, W0_h, W1_h, p_wimg);
    csr_zero<<<node_blocks, 256>>>(p_deg, p_cur, Nn);
    csr_count<<<edge_blocks, 256>>>(edges, p_deg, E);
    csr_offsets<<<node_blocks, 256>>>(p_deg, p_rs, p_wr, p_cur, Nn);
    csr_fill<<<edge_blocks, 256>>>(edges, p_wr, p_adj, E);

    // ---- Layer 1: features -> g_y1 (pre-relu; consumers apply relu) -------
    gemm_tc<0><<<gemm_grid, 256, SM_TOTAL>>>(
        features, p_wimg, b0_1, b1_1, p_y1, p_n, Nn);
    agg<<<agg_blocks, 256>>>(p_rs, p_deg, p_adj, p_n, p_y1, Nn);

    // ---- 12 hidden layers: relu folded into A conversion ------------------
    const float* src = p_y1;
    float* dst = p_ya;
    for (int l = 0; l < Lh; l++) {
        const __nv_bfloat16* wl = p_wimg + (size_t)(l + 1) * 4 * D * D;
        const float* b0 = b0_h + (size_t)l * D;
        const float* b1 = b1_h + (size_t)l * D;
        gemm_tc<1><<<gemm_grid, 256, SM_TOTAL>>>(src, wl, b0, b1, dst, p_n, Nn);
        agg<<<agg_blocks, 256>>>(p_rs, p_deg, p_adj, p_n, dst, Nn);
        src = dst;
        dst = (dst == p_ya) ? p_yb : p_ya;
    }
    const float* ylast = src;

    // ---- auxiliary output = relu(ylast) ------------------------------------
    relu_out<<<relu_blocks, 256>>>(ylast, aux, nquads);

    // ---- Final layer: (relu(y1) + relu(ylast)) -> vertices [N,3] -----------
    final_gconv<<<node_blocks, 256>>>(p_y1, ylast, W0_l, b0_l, W1_l, b1_l,
                                      vert, p_n3, Nn);
    agg3<<<node_blocks, 256>>>(p_rs, p_deg, p_adj, p_n3, vert, Nn);
}